// round 5
// baseline (speedup 1.0000x reference)
#include <cuda_runtime.h>
#include <cstdint>

#define N_CAP 50000
#define D 128
#define F_IN 256
#define C_ATT 32

typedef unsigned long long ull;

// -------- device scratch (no runtime allocation allowed) --------
__device__ float g_l_gene[N_CAP * D];
__device__ float g_r_gene[N_CAP * D];
__device__ float g_l_prot[N_CAP * D];
__device__ float g_r_prot[N_CAP * D];
__device__ float g_agg_gg[N_CAP * D];
__device__ float g_agg_gp[N_CAP * D];
__device__ float g_agg_pp[N_CAP * D];
__device__ float g_s[6 * N_CAP];      // sl0,sr0,sl1,sr1,sl2,sr2
__device__ float g_denom[3 * N_CAP];
__device__ float g_dummy[N_CAP];

// -------- packed f32x2 helpers (sm_100+) --------
__device__ __forceinline__ ull pack2(float a) {
    ull r;
    asm("mov.b64 %0, {%1, %1};" : "=l"(r) : "f"(a));
    return r;
}
__device__ __forceinline__ void fma2(ull& c, ull a, ull b) {
    asm("fma.rn.f32x2 %0, %1, %2, %0;" : "+l"(c) : "l"(a), "l"(b));
}

// ================= projection GEMM =================
// out[N,128] = X[N,256] @ W[128,256]^T + bias ; grid.y selects (Wl)/(Wr)
#define BM 128
#define BN 128
#define BK 16

__global__ __launch_bounds__(256) void proj_gemm(
    const float* __restrict__ X, int N,
    const float* __restrict__ Wl, const float* __restrict__ bl, float* __restrict__ outL,
    const float* __restrict__ Wr, const float* __restrict__ br, float* __restrict__ outR)
{
    const float* W    = blockIdx.y ? Wr : Wl;
    const float* bias = blockIdx.y ? br : bl;
    float* out        = blockIdx.y ? outR : outL;

    __shared__ float As[BK][BM + 4];
    __shared__ float Bs[BK][BN + 4];

    int t  = threadIdx.x;
    int m0 = blockIdx.x * BM;
    int tx = t & 15, ty = t >> 4;
    int lr = t >> 2;
    int lc = (t & 3) * 4;

    ull acc[8][4];
#pragma unroll
    for (int i = 0; i < 8; i++)
#pragma unroll
        for (int j = 0; j < 4; j++) acc[i][j] = 0ull;

    for (int kt = 0; kt < F_IN; kt += BK) {
#pragma unroll
        for (int p = 0; p < 2; ++p) {
            int m  = lr + p * 64;
            int gm = m0 + m; if (gm >= N) gm = N - 1;
            float4 v = *(const float4*)(X + (size_t)gm * F_IN + kt + lc);
            As[lc + 0][m] = v.x; As[lc + 1][m] = v.y;
            As[lc + 2][m] = v.z; As[lc + 3][m] = v.w;
            int n = lr + p * 64;
            float4 w = *(const float4*)(W + (size_t)n * F_IN + kt + lc);
            Bs[lc + 0][n] = w.x; Bs[lc + 1][n] = w.y;
            Bs[lc + 2][n] = w.z; Bs[lc + 3][n] = w.w;
        }
        __syncthreads();
#pragma unroll
        for (int kk = 0; kk < BK; kk++) {
            float4 a0 = *(const float4*)&As[kk][ty * 8];
            float4 a1 = *(const float4*)&As[kk][ty * 8 + 4];
            ulonglong2 bA = *(const ulonglong2*)&Bs[kk][tx * 8];
            ulonglong2 bB = *(const ulonglong2*)&Bs[kk][tx * 8 + 4];
            ull b0 = bA.x, b1 = bA.y, b2 = bB.x, b3 = bB.y;
            float av[8] = {a0.x, a0.y, a0.z, a0.w, a1.x, a1.y, a1.z, a1.w};
#pragma unroll
            for (int i = 0; i < 8; i++) {
                ull aa = pack2(av[i]);
                fma2(acc[i][0], aa, b0);
                fma2(acc[i][1], aa, b1);
                fma2(acc[i][2], aa, b2);
                fma2(acc[i][3], aa, b3);
            }
        }
        __syncthreads();
    }

    float bi[8];
    {
        float4 q0 = *(const float4*)(bias + tx * 8);
        float4 q1 = *(const float4*)(bias + tx * 8 + 4);
        bi[0] = q0.x; bi[1] = q0.y; bi[2] = q0.z; bi[3] = q0.w;
        bi[4] = q1.x; bi[5] = q1.y; bi[6] = q1.z; bi[7] = q1.w;
    }
#pragma unroll
    for (int i = 0; i < 8; i++) {
        int row = m0 + ty * 8 + i;
        if (row < N) {
            union { ull u; float2 f; } cv;
            float o[8];
#pragma unroll
            for (int j = 0; j < 4; j++) {
                cv.u = acc[i][j];
                o[2 * j]     = cv.f.x + bi[2 * j];
                o[2 * j + 1] = cv.f.y + bi[2 * j + 1];
            }
            *(float4*)(out + (size_t)row * D + tx * 8)     = make_float4(o[0], o[1], o[2], o[3]);
            *(float4*)(out + (size_t)row * D + tx * 8 + 4) = make_float4(o[4], o[5], o[6], o[7]);
        }
    }
}

// ================= fused attention scalars (GEMM-style) =================
// For up to two stacked weight-sets over the SAME feature matrix:
//   outA[n] = sum_{c<32} tanh(feat[n]·Wa[c] + ba[c]) * qa[c]
//   outB[n] = sum_{c<32} tanh(feat[n]·Wb[c] + bb[c]) * qb[c]
// Tile: BM=128 rows x 64 cols (A=cols 0..31, B=cols 32..63), BK=16, 256 threads,
// each thread owns 4 rows x 8 cols in f32x2 accumulators.
__global__ __launch_bounds__(256) void attn_fused(
    const float* __restrict__ feat, int N,
    const float* __restrict__ Wa, const float* __restrict__ ba, const float* __restrict__ qa,
    const float* __restrict__ Wb, const float* __restrict__ bb, const float* __restrict__ qb,
    float* __restrict__ outA, float* __restrict__ outB)
{
    __shared__ float As[16][128 + 4];
    __shared__ float Bs[16][64 + 4];
    __shared__ float cb[64], cq[64];

    int t  = threadIdx.x;
    int m0 = blockIdx.x * 128;

    if (t < 32)      { cb[t] = ba[t];      cq[t] = qa[t]; }
    else if (t < 64) { cb[t] = bb[t - 32]; cq[t] = qb[t - 32]; }

    int tx = t & 7, ty = t >> 3;        // 8 x 32 thread grid: 8 cols-of-8, 32 rows-of-4
    int lr = t >> 1, lc = (t & 1) * 8;  // feat tile loader: row, k-offset
    int wcol = t >> 2, wk = (t & 3) * 4; // weight tile loader
    const float* Wsel = (wcol < 32) ? (Wa + (size_t)wcol * D)
                                    : (Wb + (size_t)(wcol - 32) * D);

    ull acc[4][4];
#pragma unroll
    for (int i = 0; i < 4; i++)
#pragma unroll
        for (int j = 0; j < 4; j++) acc[i][j] = 0ull;

    int gm = m0 + lr; if (gm >= N) gm = N - 1;
    const float* frow = feat + (size_t)gm * D;

    for (int kt = 0; kt < D; kt += 16) {
        float4 v0 = *(const float4*)(frow + kt + lc);
        float4 v1 = *(const float4*)(frow + kt + lc + 4);
        As[lc + 0][lr] = v0.x; As[lc + 1][lr] = v0.y;
        As[lc + 2][lr] = v0.z; As[lc + 3][lr] = v0.w;
        As[lc + 4][lr] = v1.x; As[lc + 5][lr] = v1.y;
        As[lc + 6][lr] = v1.z; As[lc + 7][lr] = v1.w;
        float4 w = *(const float4*)(Wsel + kt + wk);
        Bs[wk + 0][wcol] = w.x; Bs[wk + 1][wcol] = w.y;
        Bs[wk + 2][wcol] = w.z; Bs[wk + 3][wcol] = w.w;
        __syncthreads();
#pragma unroll
        for (int kk = 0; kk < 16; kk++) {
            float4 a = *(const float4*)&As[kk][ty * 4];
            ulonglong2 b0 = *(const ulonglong2*)&Bs[kk][tx * 8];
            ulonglong2 b1 = *(const ulonglong2*)&Bs[kk][tx * 8 + 4];
            float av[4] = {a.x, a.y, a.z, a.w};
#pragma unroll
            for (int i = 0; i < 4; i++) {
                ull aa = pack2(av[i]);
                fma2(acc[i][0], aa, b0.x);
                fma2(acc[i][1], aa, b0.y);
                fma2(acc[i][2], aa, b1.x);
                fma2(acc[i][3], aa, b1.y);
            }
        }
        __syncthreads();
    }

    // epilogue: tanh + q-dot over this thread's 8 columns, reduce across tx
    float bcol[8], qcol[8];
#pragma unroll
    for (int j = 0; j < 8; j++) { bcol[j] = cb[tx * 8 + j]; qcol[j] = cq[tx * 8 + j]; }

#pragma unroll
    for (int i = 0; i < 4; i++) {
        float s = 0.f;
#pragma unroll
        for (int jp = 0; jp < 4; jp++) {
            union { ull u; float2 f; } cv; cv.u = acc[i][jp];
            s += tanhf(cv.f.x + bcol[2 * jp])     * qcol[2 * jp];
            s += tanhf(cv.f.y + bcol[2 * jp + 1]) * qcol[2 * jp + 1];
        }
        // tx = lane&7: reduce within each half (tx 0..3 = set A, 4..7 = set B)
        s += __shfl_xor_sync(0xffffffffu, s, 1);
        s += __shfl_xor_sync(0xffffffffu, s, 2);
        int row = m0 + ty * 4 + i;
        if (row < N) {
            if (tx == 0)      outA[row] = s;
            else if (tx == 4) outB[row] = s;
        }
    }
}

// ================= edge passes =================
// |e| <= sum|qw| < 20, so exp never overflows fp32: skip the segment-max pass.
__global__ __launch_bounds__(256) void edge_denom(
    const int* __restrict__ eidx, int E,
    const float* __restrict__ sl, const float* __restrict__ sr,
    const float* __restrict__ sharp, int mp, float* __restrict__ denom)
{
    int i = blockIdx.x * 256 + threadIdx.x;
    if (i >= E) return;
    int s = eidx[i], d2 = eidx[E + i];
    float e = (sl[s] + sr[d2]) * sharp[mp];
    atomicAdd(&denom[s], __expf(e));
}

__global__ __launch_bounds__(256) void edge_scatter(
    const int* __restrict__ eidx, int E,
    const float* __restrict__ sl, const float* __restrict__ sr,
    const float* __restrict__ sharp, int mp, const float* __restrict__ denom,
    const float* __restrict__ rtail, float* __restrict__ agg)
{
    int g = blockIdx.x * 256 + threadIdx.x;
    int w = g >> 5, lane = g & 31;
    if (w >= E) return;
    int s = eidx[w], d = eidx[E + w];
    float e = (sl[s] + sr[d]) * sharp[mp];
    float alpha = __expf(e) / (denom[s] + 1e-16f);
    float4 v = *(const float4*)(rtail + (size_t)d * D + lane * 4);
    v.x *= alpha; v.y *= alpha; v.z *= alpha; v.w *= alpha;
    float* p = agg + (size_t)s * D + lane * 4;
    asm volatile("red.global.add.v4.f32 [%0], {%1,%2,%3,%4};"
                 :: "l"(p), "f"(v.x), "f"(v.y), "f"(v.z), "f"(v.w) : "memory");
}

// ================= relation combine =================
__global__ __launch_bounds__(256) void combine_kernel(
    const float* __restrict__ a0, const float* __restrict__ a1,
    const float* __restrict__ selfe,
    const float* __restrict__ convW,
    float* __restrict__ out, int N, int two)
{
    int g = blockIdx.x * 256 + threadIdx.x;
    int w = g >> 5, lane = g & 31;
    if (w >= N) return;
    size_t off = (size_t)w * D + lane * 4;
    float4 cw = *(const float4*)(convW + lane * 4);
    float4 r0 = *(const float4*)(a0 + off);
    float4 r1 = make_float4(0.f, 0.f, 0.f, 0.f);
    if (two) r1 = *(const float4*)(a1 + off);
    float4 rs = *(const float4*)(selfe + off);
    float d0 = cw.x * r0.x + cw.y * r0.y + cw.z * r0.z + cw.w * r0.w;
    float d1 = cw.x * r1.x + cw.y * r1.y + cw.z * r1.z + cw.w * r1.w;
    float ds = cw.x * rs.x + cw.y * rs.y + cw.z * rs.z + cw.w * rs.w;
#pragma unroll
    for (int o = 16; o; o >>= 1) {
        d0 += __shfl_xor_sync(0xffffffffu, d0, o);
        d1 += __shfl_xor_sync(0xffffffffu, d1, o);
        ds += __shfl_xor_sync(0xffffffffu, ds, o);
    }
    // conv bias is identical across relations -> cancels in softmax exactly
    float m = fmaxf(d0, ds);
    if (two) m = fmaxf(m, d1);
    float e0 = __expf(d0 - m);
    float e1 = two ? __expf(d1 - m) : 0.f;
    float es = __expf(ds - m);
    float inv = 1.f / (e0 + e1 + es);
    e0 *= inv; e1 *= inv; es *= inv;
    float4 o4;
    o4.x = fmaxf(0.f, r0.x * e0 + r1.x * e1 + rs.x * es);
    o4.y = fmaxf(0.f, r0.y * e0 + r1.y * e1 + rs.y * es);
    o4.z = fmaxf(0.f, r0.z * e0 + r1.z * e1 + rs.z * es);
    o4.w = fmaxf(0.f, r0.w * e0 + r1.w * e1 + rs.w * es);
    *(float4*)(out + off) = o4;
}

// ================= launcher =================
extern "C" void kernel_launch(void* const* d_in, const int* in_sizes, int n_in,
                              void* d_out, int out_size)
{
    const float* x_gene  = (const float*)d_in[0];
    const float* x_prot  = (const float*)d_in[1];
    const float* Wl_gene = (const float*)d_in[2];
    const float* bl_gene = (const float*)d_in[3];
    const float* Wr_gene = (const float*)d_in[4];
    const float* br_gene = (const float*)d_in[5];
    const float* Wl_prot = (const float*)d_in[6];
    const float* bl_prot = (const float*)d_in[7];
    const float* Wr_prot = (const float*)d_in[8];
    const float* br_prot = (const float*)d_in[9];
    const float* alW     = (const float*)d_in[10];
    const float* alb     = (const float*)d_in[11];
    const float* arW     = (const float*)d_in[12];
    const float* arb     = (const float*)d_in[13];
    const float* qw      = (const float*)d_in[14];
    const float* sharp   = (const float*)d_in[15];
    const float* convgW  = (const float*)d_in[16];
    const float* convpW  = (const float*)d_in[18];
    const int*   e_gg    = (const int*)d_in[20];
    const int*   e_gp    = (const int*)d_in[21];
    const int*   e_pp    = (const int*)d_in[22];

    int Ng  = in_sizes[0] / F_IN;
    int Np  = in_sizes[1] / F_IN;
    int Egg = in_sizes[20] / 2;
    int Egp = in_sizes[21] / 2;
    int Epp = in_sizes[22] / 2;

    float *l_gene, *r_gene, *l_prot, *r_prot, *agg_gg, *agg_gp, *agg_pp, *sbuf, *dbuf, *dummy;
    cudaGetSymbolAddress((void**)&l_gene, g_l_gene);
    cudaGetSymbolAddress((void**)&r_gene, g_r_gene);
    cudaGetSymbolAddress((void**)&l_prot, g_l_prot);
    cudaGetSymbolAddress((void**)&r_prot, g_r_prot);
    cudaGetSymbolAddress((void**)&agg_gg, g_agg_gg);
    cudaGetSymbolAddress((void**)&agg_gp, g_agg_gp);
    cudaGetSymbolAddress((void**)&agg_pp, g_agg_pp);
    cudaGetSymbolAddress((void**)&sbuf, g_s);
    cudaGetSymbolAddress((void**)&dbuf, g_denom);
    cudaGetSymbolAddress((void**)&dummy, g_dummy);

    float* sl0 = sbuf + 0 * N_CAP; float* sr0 = sbuf + 1 * N_CAP;
    float* sl1 = sbuf + 2 * N_CAP; float* sr1 = sbuf + 3 * N_CAP;
    float* sl2 = sbuf + 4 * N_CAP; float* sr2 = sbuf + 5 * N_CAP;
    float* den0 = dbuf; float* den1 = dbuf + N_CAP; float* den2 = dbuf + 2 * N_CAP;

    cudaMemsetAsync(agg_gg, 0, (size_t)Ng * D * sizeof(float), 0);
    cudaMemsetAsync(agg_gp, 0, (size_t)Ng * D * sizeof(float), 0);
    cudaMemsetAsync(agg_pp, 0, (size_t)Np * D * sizeof(float), 0);
    cudaMemsetAsync(den0, 0, (size_t)Ng * sizeof(float), 0);
    cudaMemsetAsync(den1, 0, (size_t)Ng * sizeof(float), 0);
    cudaMemsetAsync(den2, 0, (size_t)Np * sizeof(float), 0);

    proj_gemm<<<dim3((Ng + BM - 1) / BM, 2), 256>>>(x_gene, Ng, Wl_gene, bl_gene, l_gene,
                                                    Wr_gene, br_gene, r_gene);
    proj_gemm<<<dim3((Np + BM - 1) / BM, 2), 256>>>(x_prot, Np, Wl_prot, bl_prot, l_prot,
                                                    Wr_prot, br_prot, r_prot);

    // attention scalars: qw[mp] is [2C]; first C weights pair with 'l/head', last C with 'r/tail'
    const float* alW0 = alW + 0 * C_ATT * D; const float* alW1 = alW + 1 * C_ATT * D; const float* alW2 = alW + 2 * C_ATT * D;
    const float* arW0 = arW + 0 * C_ATT * D; const float* arW1 = arW + 1 * C_ATT * D; const float* arW2 = arW + 2 * C_ATT * D;
    const float* alb0 = alb;                 const float* alb1 = alb + C_ATT;          const float* alb2 = alb + 2 * C_ATT;
    const float* arb0 = arb;                 const float* arb1 = arb + C_ATT;          const float* arb2 = arb + 2 * C_ATT;

    int gb_g = (Ng + 127) / 128, gb_p = (Np + 127) / 128;
    attn_fused<<<gb_g, 256>>>(l_gene, Ng, alW0, alb0, qw + 0 * 64,          alW1, alb1, qw + 1 * 64,          sl0, sl1);
    attn_fused<<<gb_p, 256>>>(r_prot, Np, arW1, arb1, qw + 1 * 64 + C_ATT, arW2, arb2, qw + 2 * 64 + C_ATT, sr1, sr2);
    attn_fused<<<gb_g, 256>>>(r_gene, Ng, arW0, arb0, qw + 0 * 64 + C_ATT, arW0, arb0, qw + 0 * 64 + C_ATT, sr0, dummy);
    attn_fused<<<gb_p, 256>>>(l_prot, Np, alW2, alb2, qw + 2 * 64,          alW2, alb2, qw + 2 * 64,          sl2, dummy);

    edge_denom<<<(Egg + 255) / 256, 256>>>(e_gg, Egg, sl0, sr0, sharp, 0, den0);
    edge_denom<<<(Egp + 255) / 256, 256>>>(e_gp, Egp, sl1, sr1, sharp, 1, den1);
    edge_denom<<<(Epp + 255) / 256, 256>>>(e_pp, Epp, sl2, sr2, sharp, 2, den2);

    edge_scatter<<<(unsigned)(((size_t)Egg * 32 + 255) / 256), 256>>>(e_gg, Egg, sl0, sr0, sharp, 0, den0, r_gene, agg_gg);
    edge_scatter<<<(unsigned)(((size_t)Egp * 32 + 255) / 256), 256>>>(e_gp, Egp, sl1, sr1, sharp, 1, den1, r_prot, agg_gp);
    edge_scatter<<<(unsigned)(((size_t)Epp * 32 + 255) / 256), 256>>>(e_pp, Epp, sl2, sr2, sharp, 2, den2, r_prot, agg_pp);

    float* out = (float*)d_out;
    combine_kernel<<<(unsigned)(((size_t)Ng * 32 + 255) / 256), 256>>>(agg_gg, agg_gp, l_gene, convgW, out, Ng, 1);
    combine_kernel<<<(unsigned)(((size_t)Np * 32 + 255) / 256), 256>>>(agg_pp, agg_pp, l_prot, convpW, out + (size_t)Ng * D, Np, 0);
}

// round 11
// speedup vs baseline: 1.4628x; 1.4628x over previous
#include <cuda_runtime.h>
#include <cstdint>

#define N_CAP 50000
#define D 128
#define F_IN 256
#define C_ATT 32

typedef unsigned long long ull;

// -------- device scratch (no runtime allocation allowed) --------
__device__ float g_l_gene[N_CAP * D];
__device__ float g_r_gene[N_CAP * D];
__device__ float g_l_prot[N_CAP * D];
__device__ float g_r_prot[N_CAP * D];
__device__ float g_a_gene[N_CAP * D];   // stacked attn projections (3x32 cols + 32 pad)
__device__ float g_a_prot[N_CAP * D];
__device__ float g_agg_gg[N_CAP * D];
__device__ float g_agg_gp[N_CAP * D];
__device__ float g_agg_pp[N_CAP * D];
__device__ float g_s[6 * N_CAP];        // sl0,sr0,sl1,sr1,sl2,sr2
__device__ float g_denom[3 * N_CAP];
__device__ float g_compW[2 * 128 * 256]; // composite attn weights: gene, prot
__device__ float g_compb[2 * 128];
__device__ float g_compq[2 * 128];

// -------- packed f32x2 helpers (sm_100+) --------
__device__ __forceinline__ ull pack2(float a) {
    ull r;
    asm("mov.b64 %0, {%1, %1};" : "=l"(r) : "f"(a));
    return r;
}
__device__ __forceinline__ void fma2(ull& c, ull a, ull b) {
    asm("fma.rn.f32x2 %0, %1, %2, %0;" : "+l"(c) : "l"(a), "l"(b));
}

// ================= projection GEMM =================
// out[N,128] = X[N,256] @ W[128,256]^T + bias ; grid.y selects (Wl)/(Wr)
#define BM 128
#define BN 128
#define BK 16

__global__ __launch_bounds__(256) void proj_gemm(
    const float* __restrict__ X, int N,
    const float* __restrict__ Wl, const float* __restrict__ bl, float* __restrict__ outL,
    const float* __restrict__ Wr, const float* __restrict__ br, float* __restrict__ outR)
{
    const float* W    = blockIdx.y ? Wr : Wl;
    const float* bias = blockIdx.y ? br : bl;
    float* out        = blockIdx.y ? outR : outL;

    __shared__ float As[BK][BM + 4];
    __shared__ float Bs[BK][BN + 4];

    int t  = threadIdx.x;
    int m0 = blockIdx.x * BM;
    int tx = t & 15, ty = t >> 4;
    int lr = t >> 2;
    int lc = (t & 3) * 4;

    ull acc[8][4];
#pragma unroll
    for (int i = 0; i < 8; i++)
#pragma unroll
        for (int j = 0; j < 4; j++) acc[i][j] = 0ull;

    for (int kt = 0; kt < F_IN; kt += BK) {
#pragma unroll
        for (int p = 0; p < 2; ++p) {
            int m  = lr + p * 64;
            int gm = m0 + m; if (gm >= N) gm = N - 1;
            float4 v = *(const float4*)(X + (size_t)gm * F_IN + kt + lc);
            As[lc + 0][m] = v.x; As[lc + 1][m] = v.y;
            As[lc + 2][m] = v.z; As[lc + 3][m] = v.w;
            int n = lr + p * 64;
            float4 w = *(const float4*)(W + (size_t)n * F_IN + kt + lc);
            Bs[lc + 0][n] = w.x; Bs[lc + 1][n] = w.y;
            Bs[lc + 2][n] = w.z; Bs[lc + 3][n] = w.w;
        }
        __syncthreads();
#pragma unroll
        for (int kk = 0; kk < BK; kk++) {
            float4 a0 = *(const float4*)&As[kk][ty * 8];
            float4 a1 = *(const float4*)&As[kk][ty * 8 + 4];
            ulonglong2 bA = *(const ulonglong2*)&Bs[kk][tx * 8];
            ulonglong2 bB = *(const ulonglong2*)&Bs[kk][tx * 8 + 4];
            ull b0 = bA.x, b1 = bA.y, b2 = bB.x, b3 = bB.y;
            float av[8] = {a0.x, a0.y, a0.z, a0.w, a1.x, a1.y, a1.z, a1.w};
#pragma unroll
            for (int i = 0; i < 8; i++) {
                ull aa = pack2(av[i]);
                fma2(acc[i][0], aa, b0);
                fma2(acc[i][1], aa, b1);
                fma2(acc[i][2], aa, b2);
                fma2(acc[i][3], aa, b3);
            }
        }
        __syncthreads();
    }

    float bi[8];
    {
        float4 q0 = *(const float4*)(bias + tx * 8);
        float4 q1 = *(const float4*)(bias + tx * 8 + 4);
        bi[0] = q0.x; bi[1] = q0.y; bi[2] = q0.z; bi[3] = q0.w;
        bi[4] = q1.x; bi[5] = q1.y; bi[6] = q1.z; bi[7] = q1.w;
    }
#pragma unroll
    for (int i = 0; i < 8; i++) {
        int row = m0 + ty * 8 + i;
        if (row < N) {
            union { ull u; float2 f; } cv;
            float o[8];
#pragma unroll
            for (int j = 0; j < 4; j++) {
                cv.u = acc[i][j];
                o[2 * j]     = cv.f.x + bi[2 * j];
                o[2 * j + 1] = cv.f.y + bi[2 * j + 1];
            }
            *(float4*)(out + (size_t)row * D + tx * 8)     = make_float4(o[0], o[1], o[2], o[3]);
            *(float4*)(out + (size_t)row * D + tx * 8 + 4) = make_float4(o[4], o[5], o[6], o[7]);
        }
    }
}

// ================= composite attention weight builder =================
// compW[row,:] = attnW_row[1x128] @ nodeW[128x256]; compb = attnW_row@node_b + attn_b;
// compq[row] = matching qw entry. 192 blocks: set = bx>>5 in 0..5, c = bx&31.
// Gene sets (rows): 0-31: sl0 (alW0@Wl_g), 32-63: sl1 (alW1@Wl_g), 64-95: sr0 (arW0@Wr_g)
// Prot sets (rows): 0-31: sr1 (arW1@Wr_p), 32-63: sr2 (arW2@Wr_p), 64-95: sl2 (alW2@Wl_p)
__global__ __launch_bounds__(256) void build_comp(
    const float* __restrict__ alW, const float* __restrict__ alb,
    const float* __restrict__ arW, const float* __restrict__ arb,
    const float* __restrict__ qw,
    const float* __restrict__ Wl_gene, const float* __restrict__ bl_gene,
    const float* __restrict__ Wr_gene, const float* __restrict__ br_gene,
    const float* __restrict__ Wl_prot, const float* __restrict__ bl_prot,
    const float* __restrict__ Wr_prot, const float* __restrict__ br_prot,
    float* __restrict__ compWg, float* __restrict__ compbg, float* __restrict__ compqg,
    float* __restrict__ compWp, float* __restrict__ compbp, float* __restrict__ compqp)
{
    int bx = blockIdx.x;
    int set = bx >> 5, c = bx & 31;
    const float *A, *X, *batt, *bn, *q;
    float *dW, *db, *dq;
    int row;
    switch (set) {
        case 0:  A = alW + c * 128;            X = Wl_gene; batt = alb;      bn = bl_gene; q = qw;            dW = compWg; db = compbg; dq = compqg; row = c;      break;
        case 1:  A = alW + 32 * 128 + c * 128; X = Wl_gene; batt = alb + 32; bn = bl_gene; q = qw + 64;       dW = compWg; db = compbg; dq = compqg; row = 32 + c; break;
        case 2:  A = arW + c * 128;            X = Wr_gene; batt = arb;      bn = br_gene; q = qw + 32;       dW = compWg; db = compbg; dq = compqg; row = 64 + c; break;
        case 3:  A = arW + 32 * 128 + c * 128; X = Wr_prot; batt = arb + 32; bn = br_prot; q = qw + 64 + 32;  dW = compWp; db = compbp; dq = compqp; row = c;      break;
        case 4:  A = arW + 64 * 128 + c * 128; X = Wr_prot; batt = arb + 64; bn = br_prot; q = qw + 128 + 32; dW = compWp; db = compbp; dq = compqp; row = 32 + c; break;
        default: A = alW + 64 * 128 + c * 128; X = Wl_prot; batt = alb + 64; bn = bl_prot; q = qw + 128;      dW = compWp; db = compbp; dq = compqp; row = 64 + c; break;
    }
    int f = threadIdx.x;
    float acc = 0.f;
#pragma unroll 8
    for (int k = 0; k < 128; k++)
        acc += __ldg(A + k) * __ldg(X + (size_t)k * 256 + f);
    dW[(size_t)row * 256 + f] = acc;
    if (f == 0) {
        float bacc = batt[c];
        for (int k = 0; k < 128; k++) bacc += A[k] * bn[k];
        db[row] = bacc;
        dq[row] = q[c];
    }
}

// ================= s extraction =================
// s_g[n] = sum_{lane} tanh(a[n, g*32+lane]) * q[g*32+lane], g=0,1,2. Warp per node.
__global__ __launch_bounds__(256) void s_extract(
    const float* __restrict__ a, int N, const float* __restrict__ q,
    float* __restrict__ s0, float* __restrict__ s1, float* __restrict__ s2)
{
    int n = blockIdx.x * 8 + (threadIdx.x >> 5);
    if (n >= N) return;
    int lane = threadIdx.x & 31;
    const float* base = a + (size_t)n * D;
    float v0 = tanhf(base[lane])      * __ldg(q + lane);
    float v1 = tanhf(base[32 + lane]) * __ldg(q + 32 + lane);
    float v2 = tanhf(base[64 + lane]) * __ldg(q + 64 + lane);
#pragma unroll
    for (int o = 16; o; o >>= 1) {
        v0 += __shfl_xor_sync(0xffffffffu, v0, o);
        v1 += __shfl_xor_sync(0xffffffffu, v1, o);
        v2 += __shfl_xor_sync(0xffffffffu, v2, o);
    }
    if (lane == 0) { s0[n] = v0; s1[n] = v1; s2[n] = v2; }
}

// ================= fused edge pass =================
// |e| <= sum|qw| < 20, so exp never overflows fp32: skip the segment-max pass.
// Scatters UNNORMALIZED exp(e)*v into agg and exp(e) into denom; the combine
// kernel divides by denom (identical algebra: all edges of a segment share denom).
__global__ __launch_bounds__(256) void edge_scatter(
    const int* __restrict__ eidx, int E,
    const float* __restrict__ sl, const float* __restrict__ sr,
    const float* __restrict__ sharp, int mp,
    const float* __restrict__ rtail, float* __restrict__ agg,
    float* __restrict__ denom)
{
    int g = blockIdx.x * 256 + threadIdx.x;
    int w = g >> 5, lane = g & 31;
    if (w >= E) return;
    int s = eidx[w], d = eidx[E + w];
    float ew = __expf((__ldg(sl + s) + __ldg(sr + d)) * __ldg(sharp + mp));
    if (lane == 0) {
        asm volatile("red.global.add.f32 [%0], %1;" :: "l"(denom + s), "f"(ew) : "memory");
    }
    float4 v = *(const float4*)(rtail + (size_t)d * D + lane * 4);
    v.x *= ew; v.y *= ew; v.z *= ew; v.w *= ew;
    float* p = agg + (size_t)s * D + lane * 4;
    asm volatile("red.global.add.v4.f32 [%0], {%1,%2,%3,%4};"
                 :: "l"(p), "f"(v.x), "f"(v.y), "f"(v.z), "f"(v.w) : "memory");
}

// ================= relation combine =================
// Normalizes the unnormalized aggregates by their softmax denominators here.
__global__ __launch_bounds__(256) void combine_kernel(
    const float* __restrict__ a0, const float* __restrict__ a1,
    const float* __restrict__ selfe,
    const float* __restrict__ convW,
    const float* __restrict__ den0, const float* __restrict__ den1,
    float* __restrict__ out, int N, int two)
{
    int g = blockIdx.x * 256 + threadIdx.x;
    int w = g >> 5, lane = g & 31;
    if (w >= N) return;
    size_t off = (size_t)w * D + lane * 4;
    float inv0 = 1.f / (den0[w] + 1e-16f);
    float inv1 = two ? 1.f / (den1[w] + 1e-16f) : 0.f;
    float4 cw = *(const float4*)(convW + lane * 4);
    float4 r0 = *(const float4*)(a0 + off);
    r0.x *= inv0; r0.y *= inv0; r0.z *= inv0; r0.w *= inv0;
    float4 r1 = make_float4(0.f, 0.f, 0.f, 0.f);
    if (two) {
        r1 = *(const float4*)(a1 + off);
        r1.x *= inv1; r1.y *= inv1; r1.z *= inv1; r1.w *= inv1;
    }
    float4 rs = *(const float4*)(selfe + off);
    float d0 = cw.x * r0.x + cw.y * r0.y + cw.z * r0.z + cw.w * r0.w;
    float d1 = cw.x * r1.x + cw.y * r1.y + cw.z * r1.z + cw.w * r1.w;
    float ds = cw.x * rs.x + cw.y * rs.y + cw.z * rs.z + cw.w * rs.w;
#pragma unroll
    for (int o = 16; o; o >>= 1) {
        d0 += __shfl_xor_sync(0xffffffffu, d0, o);
        d1 += __shfl_xor_sync(0xffffffffu, d1, o);
        ds += __shfl_xor_sync(0xffffffffu, ds, o);
    }
    // conv bias is identical across relations -> cancels in softmax exactly
    float m = fmaxf(d0, ds);
    if (two) m = fmaxf(m, d1);
    float e0 = __expf(d0 - m);
    float e1 = two ? __expf(d1 - m) : 0.f;
    float es = __expf(ds - m);
    float inv = 1.f / (e0 + e1 + es);
    e0 *= inv; e1 *= inv; es *= inv;
    float4 o4;
    o4.x = fmaxf(0.f, r0.x * e0 + r1.x * e1 + rs.x * es);
    o4.y = fmaxf(0.f, r0.y * e0 + r1.y * e1 + rs.y * es);
    o4.z = fmaxf(0.f, r0.z * e0 + r1.z * e1 + rs.z * es);
    o4.w = fmaxf(0.f, r0.w * e0 + r1.w * e1 + rs.w * es);
    *(float4*)(out + off) = o4;
}

// ================= launcher =================
extern "C" void kernel_launch(void* const* d_in, const int* in_sizes, int n_in,
                              void* d_out, int out_size)
{
    const float* x_gene  = (const float*)d_in[0];
    const float* x_prot  = (const float*)d_in[1];
    const float* Wl_gene = (const float*)d_in[2];
    const float* bl_gene = (const float*)d_in[3];
    const float* Wr_gene = (const float*)d_in[4];
    const float* br_gene = (const float*)d_in[5];
    const float* Wl_prot = (const float*)d_in[6];
    const float* bl_prot = (const float*)d_in[7];
    const float* Wr_prot = (const float*)d_in[8];
    const float* br_prot = (const float*)d_in[9];
    const float* alW     = (const float*)d_in[10];
    const float* alb     = (const float*)d_in[11];
    const float* arW     = (const float*)d_in[12];
    const float* arb     = (const float*)d_in[13];
    const float* qw      = (const float*)d_in[14];
    const float* sharp   = (const float*)d_in[15];
    const float* convgW  = (const float*)d_in[16];
    const float* convpW  = (const float*)d_in[18];
    const int*   e_gg    = (const int*)d_in[20];
    const int*   e_gp    = (const int*)d_in[21];
    const int*   e_pp    = (const int*)d_in[22];

    int Ng  = in_sizes[0] / F_IN;
    int Np  = in_sizes[1] / F_IN;
    int Egg = in_sizes[20] / 2;
    int Egp = in_sizes[21] / 2;
    int Epp = in_sizes[22] / 2;

    float *l_gene, *r_gene, *l_prot, *r_prot, *a_gene, *a_prot;
    float *agg_gg, *agg_gp, *agg_pp, *sbuf, *dbuf, *compW, *compb, *compq;
    cudaGetSymbolAddress((void**)&l_gene, g_l_gene);
    cudaGetSymbolAddress((void**)&r_gene, g_r_gene);
    cudaGetSymbolAddress((void**)&l_prot, g_l_prot);
    cudaGetSymbolAddress((void**)&r_prot, g_r_prot);
    cudaGetSymbolAddress((void**)&a_gene, g_a_gene);
    cudaGetSymbolAddress((void**)&a_prot, g_a_prot);
    cudaGetSymbolAddress((void**)&agg_gg, g_agg_gg);
    cudaGetSymbolAddress((void**)&agg_gp, g_agg_gp);
    cudaGetSymbolAddress((void**)&agg_pp, g_agg_pp);
    cudaGetSymbolAddress((void**)&sbuf, g_s);
    cudaGetSymbolAddress((void**)&dbuf, g_denom);
    cudaGetSymbolAddress((void**)&compW, g_compW);
    cudaGetSymbolAddress((void**)&compb, g_compb);
    cudaGetSymbolAddress((void**)&compq, g_compq);

    float* compWg = compW;               float* compWp = compW + 128 * 256;
    float* compbg = compb;               float* compbp = compb + 128;
    float* compqg = compq;               float* compqp = compq + 128;

    float* sl0 = sbuf + 0 * N_CAP; float* sr0 = sbuf + 1 * N_CAP;
    float* sl1 = sbuf + 2 * N_CAP; float* sr1 = sbuf + 3 * N_CAP;
    float* sl2 = sbuf + 4 * N_CAP; float* sr2 = sbuf + 5 * N_CAP;
    float* den0 = dbuf; float* den1 = dbuf + N_CAP; float* den2 = dbuf + 2 * N_CAP;

    cudaMemsetAsync(agg_gg, 0, (size_t)Ng * D * sizeof(float), 0);
    cudaMemsetAsync(agg_gp, 0, (size_t)Ng * D * sizeof(float), 0);
    cudaMemsetAsync(agg_pp, 0, (size_t)Np * D * sizeof(float), 0);
    cudaMemsetAsync(dbuf, 0, (size_t)3 * N_CAP * sizeof(float), 0);
    cudaMemsetAsync(compW, 0, (size_t)2 * 128 * 256 * sizeof(float), 0);
    cudaMemsetAsync(compb, 0, (size_t)2 * 128 * sizeof(float), 0);
    cudaMemsetAsync(compq, 0, (size_t)2 * 128 * sizeof(float), 0);

    build_comp<<<192, 256>>>(alW, alb, arW, arb, qw,
                             Wl_gene, bl_gene, Wr_gene, br_gene,
                             Wl_prot, bl_prot, Wr_prot, br_prot,
                             compWg, compbg, compqg, compWp, compbp, compqp);

    int nbg = (Ng + BM - 1) / BM, nbp = (Np + BM - 1) / BM;
    proj_gemm<<<dim3(nbg, 2), 256>>>(x_gene, Ng, Wl_gene, bl_gene, l_gene,
                                     Wr_gene, br_gene, r_gene);
    proj_gemm<<<dim3(nbp, 2), 256>>>(x_prot, Np, Wl_prot, bl_prot, l_prot,
                                     Wr_prot, br_prot, r_prot);
    proj_gemm<<<dim3(nbg, 1), 256>>>(x_gene, Ng, compWg, compbg, a_gene,
                                     compWg, compbg, a_gene);
    proj_gemm<<<dim3(nbp, 1), 256>>>(x_prot, Np, compWp, compbp, a_prot,
                                     compWp, compbp, a_prot);

    s_extract<<<(Ng + 7) / 8, 256>>>(a_gene, Ng, compqg, sl0, sl1, sr0);
    s_extract<<<(Np + 7) / 8, 256>>>(a_prot, Np, compqp, sr1, sr2, sl2);

    edge_scatter<<<(unsigned)(((size_t)Egg * 32 + 255) / 256), 256>>>(e_gg, Egg, sl0, sr0, sharp, 0, r_gene, agg_gg, den0);
    edge_scatter<<<(unsigned)(((size_t)Egp * 32 + 255) / 256), 256>>>(e_gp, Egp, sl1, sr1, sharp, 1, r_prot, agg_gp, den1);
    edge_scatter<<<(unsigned)(((size_t)Epp * 32 + 255) / 256), 256>>>(e_pp, Epp, sl2, sr2, sharp, 2, r_prot, agg_pp, den2);

    float* out = (float*)d_out;
    combine_kernel<<<(unsigned)(((size_t)Ng * 32 + 255) / 256), 256>>>(agg_gg, agg_gp, l_gene, convgW, den0, den1, out, Ng, 1);
    combine_kernel<<<(unsigned)(((size_t)Np * 32 + 255) / 256), 256>>>(agg_pp, agg_pp, l_prot, convpW, den2, den2, out + (size_t)Ng * D, Np, 0);
}

// round 12
// speedup vs baseline: 1.4687x; 1.0040x over previous
#include <cuda_runtime.h>
#include <cstdint>

#define N_CAP 50000
#define E_CAP 600000
#define D 128
#define F_IN 256
#define C_ATT 32

typedef unsigned long long ull;

// -------- device scratch (no runtime allocation allowed) --------
__device__ float g_l_gene[N_CAP * D];
__device__ float g_r_gene[N_CAP * D];
__device__ float g_l_prot[N_CAP * D];
__device__ float g_r_prot[N_CAP * D];
__device__ float g_a_gene[N_CAP * D];   // stacked attn projections
__device__ float g_a_prot[N_CAP * D];
__device__ float g_agg_gg[N_CAP * D];
__device__ float g_agg_gp[N_CAP * D];
__device__ float g_agg_pp[N_CAP * D];
__device__ float g_u[3 * N_CAP];        // u0 (gene tails), u1 (prot tails mp1), u2 (prot tails mp2)
__device__ float g_compW[2 * 128 * 256];
__device__ float g_compb[2 * 128];
__device__ float g_compq[2 * 128];
__device__ int   g_cnt[3 * N_CAP];
__device__ int   g_rowptr[3 * N_CAP];
__device__ int   g_cursor[3 * N_CAP];
__device__ int   g_sdst[3 * E_CAP];

// -------- packed f32x2 helpers (sm_100+) --------
__device__ __forceinline__ ull pack2(float a) {
    ull r;
    asm("mov.b64 %0, {%1, %1};" : "=l"(r) : "f"(a));
    return r;
}
__device__ __forceinline__ void fma2(ull& c, ull a, ull b) {
    asm("fma.rn.f32x2 %0, %1, %2, %0;" : "+l"(c) : "l"(a), "l"(b));
}

// ================= projection GEMM =================
#define BM 128
#define BN 128
#define BK 16

__global__ __launch_bounds__(256) void proj_gemm(
    const float* __restrict__ X, int N,
    const float* __restrict__ Wl, const float* __restrict__ bl, float* __restrict__ outL,
    const float* __restrict__ Wr, const float* __restrict__ br, float* __restrict__ outR)
{
    const float* W    = blockIdx.y ? Wr : Wl;
    const float* bias = blockIdx.y ? br : bl;
    float* out        = blockIdx.y ? outR : outL;

    __shared__ float As[BK][BM + 4];
    __shared__ float Bs[BK][BN + 4];

    int t  = threadIdx.x;
    int m0 = blockIdx.x * BM;
    int tx = t & 15, ty = t >> 4;
    int lr = t >> 2;
    int lc = (t & 3) * 4;

    ull acc[8][4];
#pragma unroll
    for (int i = 0; i < 8; i++)
#pragma unroll
        for (int j = 0; j < 4; j++) acc[i][j] = 0ull;

    for (int kt = 0; kt < F_IN; kt += BK) {
#pragma unroll
        for (int p = 0; p < 2; ++p) {
            int m  = lr + p * 64;
            int gm = m0 + m; if (gm >= N) gm = N - 1;
            float4 v = *(const float4*)(X + (size_t)gm * F_IN + kt + lc);
            As[lc + 0][m] = v.x; As[lc + 1][m] = v.y;
            As[lc + 2][m] = v.z; As[lc + 3][m] = v.w;
            int n = lr + p * 64;
            float4 w = *(const float4*)(W + (size_t)n * F_IN + kt + lc);
            Bs[lc + 0][n] = w.x; Bs[lc + 1][n] = w.y;
            Bs[lc + 2][n] = w.z; Bs[lc + 3][n] = w.w;
        }
        __syncthreads();
#pragma unroll
        for (int kk = 0; kk < BK; kk++) {
            float4 a0 = *(const float4*)&As[kk][ty * 8];
            float4 a1 = *(const float4*)&As[kk][ty * 8 + 4];
            ulonglong2 bA = *(const ulonglong2*)&Bs[kk][tx * 8];
            ulonglong2 bB = *(const ulonglong2*)&Bs[kk][tx * 8 + 4];
            ull b0 = bA.x, b1 = bA.y, b2 = bB.x, b3 = bB.y;
            float av[8] = {a0.x, a0.y, a0.z, a0.w, a1.x, a1.y, a1.z, a1.w};
#pragma unroll
            for (int i = 0; i < 8; i++) {
                ull aa = pack2(av[i]);
                fma2(acc[i][0], aa, b0);
                fma2(acc[i][1], aa, b1);
                fma2(acc[i][2], aa, b2);
                fma2(acc[i][3], aa, b3);
            }
        }
        __syncthreads();
    }

    float bi[8];
    {
        float4 q0 = *(const float4*)(bias + tx * 8);
        float4 q1 = *(const float4*)(bias + tx * 8 + 4);
        bi[0] = q0.x; bi[1] = q0.y; bi[2] = q0.z; bi[3] = q0.w;
        bi[4] = q1.x; bi[5] = q1.y; bi[6] = q1.z; bi[7] = q1.w;
    }
#pragma unroll
    for (int i = 0; i < 8; i++) {
        int row = m0 + ty * 8 + i;
        if (row < N) {
            union { ull u; float2 f; } cv;
            float o[8];
#pragma unroll
            for (int j = 0; j < 4; j++) {
                cv.u = acc[i][j];
                o[2 * j]     = cv.f.x + bi[2 * j];
                o[2 * j + 1] = cv.f.y + bi[2 * j + 1];
            }
            *(float4*)(out + (size_t)row * D + tx * 8)     = make_float4(o[0], o[1], o[2], o[3]);
            *(float4*)(out + (size_t)row * D + tx * 8 + 4) = make_float4(o[4], o[5], o[6], o[7]);
        }
    }
}

// ================= composite attention weight builder =================
// Gene rows: 0-31: sl0, 32-63: sl1, 64-95: sr0 (only sr0 consumed downstream)
// Prot rows: 0-31: sr1, 32-63: sr2, 64-95: sl2 (sr1, sr2 consumed)
__global__ __launch_bounds__(256) void build_comp(
    const float* __restrict__ alW, const float* __restrict__ alb,
    const float* __restrict__ arW, const float* __restrict__ arb,
    const float* __restrict__ qw,
    const float* __restrict__ Wl_gene, const float* __restrict__ bl_gene,
    const float* __restrict__ Wr_gene, const float* __restrict__ br_gene,
    const float* __restrict__ Wl_prot, const float* __restrict__ bl_prot,
    const float* __restrict__ Wr_prot, const float* __restrict__ br_prot,
    float* __restrict__ compWg, float* __restrict__ compbg, float* __restrict__ compqg,
    float* __restrict__ compWp, float* __restrict__ compbp, float* __restrict__ compqp)
{
    int bx = blockIdx.x;
    int set = bx >> 5, c = bx & 31;
    const float *A, *X, *batt, *bn, *q;
    float *dW, *db, *dq;
    int row;
    switch (set) {
        case 0:  A = alW + c * 128;            X = Wl_gene; batt = alb;      bn = bl_gene; q = qw;            dW = compWg; db = compbg; dq = compqg; row = c;      break;
        case 1:  A = alW + 32 * 128 + c * 128; X = Wl_gene; batt = alb + 32; bn = bl_gene; q = qw + 64;       dW = compWg; db = compbg; dq = compqg; row = 32 + c; break;
        case 2:  A = arW + c * 128;            X = Wr_gene; batt = arb;      bn = br_gene; q = qw + 32;       dW = compWg; db = compbg; dq = compqg; row = 64 + c; break;
        case 3:  A = arW + 32 * 128 + c * 128; X = Wr_prot; batt = arb + 32; bn = br_prot; q = qw + 64 + 32;  dW = compWp; db = compbp; dq = compqp; row = c;      break;
        case 4:  A = arW + 64 * 128 + c * 128; X = Wr_prot; batt = arb + 64; bn = br_prot; q = qw + 128 + 32; dW = compWp; db = compbp; dq = compqp; row = 32 + c; break;
        default: A = alW + 64 * 128 + c * 128; X = Wl_prot; batt = alb + 64; bn = bl_prot; q = qw + 128;      dW = compWp; db = compbp; dq = compqp; row = 64 + c; break;
    }
    int f = threadIdx.x;
    float acc = 0.f;
#pragma unroll 8
    for (int k = 0; k < 128; k++)
        acc += __ldg(A + k) * __ldg(X + (size_t)k * 256 + f);
    dW[(size_t)row * 256 + f] = acc;
    if (f == 0) {
        float bacc = batt[c];
        for (int k = 0; k < 128; k++) bacc += A[k] * bn[k];
        db[row] = bacc;
        dq[row] = q[c];
    }
}

// ================= u extraction =================
// sl cancels in segment softmax, so only tail-side scores are needed:
//   u[n] = exp( sharp * sum_lane tanh(a[n,col0+lane]) * q[col0+lane] )
// gene=1: u0 from cols 64..95 (sharp[0]).  gene=0: u1 cols 0..31 (sharp[1]), u2 cols 32..63 (sharp[2]).
__global__ __launch_bounds__(256) void u_extract(
    const float* __restrict__ a, int N, const float* __restrict__ q,
    const float* __restrict__ sharp, int gene,
    float* __restrict__ u0, float* __restrict__ u1, float* __restrict__ u2)
{
    int n = blockIdx.x * 8 + (threadIdx.x >> 5);
    if (n >= N) return;
    int lane = threadIdx.x & 31;
    const float* base = a + (size_t)n * D;
    if (gene) {
        float v = tanhf(base[64 + lane]) * __ldg(q + 64 + lane);
#pragma unroll
        for (int o = 16; o; o >>= 1) v += __shfl_xor_sync(0xffffffffu, v, o);
        if (lane == 0) u0[n] = __expf(v * __ldg(sharp + 0));
    } else {
        float v1 = tanhf(base[lane])      * __ldg(q + lane);
        float v2 = tanhf(base[32 + lane]) * __ldg(q + 32 + lane);
#pragma unroll
        for (int o = 16; o; o >>= 1) {
            v1 += __shfl_xor_sync(0xffffffffu, v1, o);
            v2 += __shfl_xor_sync(0xffffffffu, v2, o);
        }
        if (lane == 0) {
            u1[n] = __expf(v1 * __ldg(sharp + 1));
            u2[n] = __expf(v2 * __ldg(sharp + 2));
        }
    }
}

// ================= CSR build =================
__global__ __launch_bounds__(256) void edge_hist(
    const int* __restrict__ eidx, int E, int* __restrict__ cnt)
{
    int i = blockIdx.x * 256 + threadIdx.x;
    if (i < E) atomicAdd(&cnt[eidx[i]], 1);
}

// one block (1024 threads) per metapath: exclusive scan of cnt -> rowptr, cursor
__global__ __launch_bounds__(1024) void scan3(
    const int* __restrict__ cnt, int* __restrict__ rowptr, int* __restrict__ cursor, int N)
{
    int mp = blockIdx.x;
    const int* c = cnt + mp * N_CAP;
    int* rp = rowptr + mp * N_CAP;
    int* cu = cursor + mp * N_CAP;
    __shared__ int part[1024];
    int t = threadIdx.x;
    int chunk = (N + 1023) / 1024;
    int lo = t * chunk, hi = min(lo + chunk, N);
    int s = 0;
    for (int j = lo; j < hi; j++) s += c[j];
    part[t] = s;
    __syncthreads();
    for (int off = 1; off < 1024; off <<= 1) {
        int v = (t >= off) ? part[t - off] : 0;
        __syncthreads();
        part[t] += v;
        __syncthreads();
    }
    int run = (t == 0) ? 0 : part[t - 1];
    for (int j = lo; j < hi; j++) {
        rp[j] = run; cu[j] = run;
        run += c[j];
    }
}

__global__ __launch_bounds__(256) void edge_scatter_idx(
    const int* __restrict__ eidx, int E, int* __restrict__ cursor, int* __restrict__ sdst)
{
    int i = blockIdx.x * 256 + threadIdx.x;
    if (i >= E) return;
    int s = eidx[i], d = eidx[E + i];
    int pos = atomicAdd(&cursor[s], 1);
    sdst[pos] = d;
}

// ================= CSR gather-aggregate =================
// warp per segment node: agg[s] = sum_d u[d]*r[d] / sum_d u[d]  (no atomics)
__global__ __launch_bounds__(256) void agg_gather(
    const int* __restrict__ rowptr, const int* __restrict__ cnt,
    const int* __restrict__ sdst,
    const float* __restrict__ u, const float* __restrict__ r,
    float* __restrict__ agg, int N)
{
    int g = blockIdx.x * 256 + threadIdx.x;
    int w = g >> 5, lane = g & 31;
    if (w >= N) return;
    int beg = rowptr[w], num = cnt[w];
    float ax = 0.f, ay = 0.f, az = 0.f, aw2 = 0.f, den = 0.f;
    int j = 0;
    for (; j + 2 <= num; j += 2) {
        int d0 = __ldg(sdst + beg + j);
        int d1 = __ldg(sdst + beg + j + 1);
        float uu0 = __ldg(u + d0);
        float uu1 = __ldg(u + d1);
        float4 v0 = *(const float4*)(r + (size_t)d0 * D + lane * 4);
        float4 v1 = *(const float4*)(r + (size_t)d1 * D + lane * 4);
        den += uu0 + uu1;
        ax += uu0 * v0.x + uu1 * v1.x;
        ay += uu0 * v0.y + uu1 * v1.y;
        az += uu0 * v0.z + uu1 * v1.z;
        aw2 += uu0 * v0.w + uu1 * v1.w;
    }
    if (j < num) {
        int d0 = __ldg(sdst + beg + j);
        float uu0 = __ldg(u + d0);
        float4 v0 = *(const float4*)(r + (size_t)d0 * D + lane * 4);
        den += uu0;
        ax += uu0 * v0.x; ay += uu0 * v0.y; az += uu0 * v0.z; aw2 += uu0 * v0.w;
    }
    float inv = (num > 0) ? 1.f / den : 0.f;
    *(float4*)(agg + (size_t)w * D + lane * 4) =
        make_float4(ax * inv, ay * inv, az * inv, aw2 * inv);
}

// ================= relation combine (inputs already normalized) =================
__global__ __launch_bounds__(256) void combine_kernel(
    const float* __restrict__ a0, const float* __restrict__ a1,
    const float* __restrict__ selfe,
    const float* __restrict__ convW,
    float* __restrict__ out, int N, int two)
{
    int g = blockIdx.x * 256 + threadIdx.x;
    int w = g >> 5, lane = g & 31;
    if (w >= N) return;
    size_t off = (size_t)w * D + lane * 4;
    float4 cw = *(const float4*)(convW + lane * 4);
    float4 r0 = *(const float4*)(a0 + off);
    float4 r1 = make_float4(0.f, 0.f, 0.f, 0.f);
    if (two) r1 = *(const float4*)(a1 + off);
    float4 rs = *(const float4*)(selfe + off);
    float d0 = cw.x * r0.x + cw.y * r0.y + cw.z * r0.z + cw.w * r0.w;
    float d1 = cw.x * r1.x + cw.y * r1.y + cw.z * r1.z + cw.w * r1.w;
    float ds = cw.x * rs.x + cw.y * rs.y + cw.z * rs.z + cw.w * rs.w;
#pragma unroll
    for (int o = 16; o; o >>= 1) {
        d0 += __shfl_xor_sync(0xffffffffu, d0, o);
        d1 += __shfl_xor_sync(0xffffffffu, d1, o);
        ds += __shfl_xor_sync(0xffffffffu, ds, o);
    }
    // conv bias is identical across relations -> cancels in softmax exactly
    float m = fmaxf(d0, ds);
    if (two) m = fmaxf(m, d1);
    float e0 = __expf(d0 - m);
    float e1 = two ? __expf(d1 - m) : 0.f;
    float es = __expf(ds - m);
    float inv = 1.f / (e0 + e1 + es);
    e0 *= inv; e1 *= inv; es *= inv;
    float4 o4;
    o4.x = fmaxf(0.f, r0.x * e0 + r1.x * e1 + rs.x * es);
    o4.y = fmaxf(0.f, r0.y * e0 + r1.y * e1 + rs.y * es);
    o4.z = fmaxf(0.f, r0.z * e0 + r1.z * e1 + rs.z * es);
    o4.w = fmaxf(0.f, r0.w * e0 + r1.w * e1 + rs.w * es);
    *(float4*)(out + off) = o4;
}

// ================= launcher =================
extern "C" void kernel_launch(void* const* d_in, const int* in_sizes, int n_in,
                              void* d_out, int out_size)
{
    const float* x_gene  = (const float*)d_in[0];
    const float* x_prot  = (const float*)d_in[1];
    const float* Wl_gene = (const float*)d_in[2];
    const float* bl_gene = (const float*)d_in[3];
    const float* Wr_gene = (const float*)d_in[4];
    const float* br_gene = (const float*)d_in[5];
    const float* Wl_prot = (const float*)d_in[6];
    const float* bl_prot = (const float*)d_in[7];
    const float* Wr_prot = (const float*)d_in[8];
    const float* br_prot = (const float*)d_in[9];
    const float* alW     = (const float*)d_in[10];
    const float* alb     = (const float*)d_in[11];
    const float* arW     = (const float*)d_in[12];
    const float* arb     = (const float*)d_in[13];
    const float* qw      = (const float*)d_in[14];
    const float* sharp   = (const float*)d_in[15];
    const float* convgW  = (const float*)d_in[16];
    const float* convpW  = (const float*)d_in[18];
    const int*   e_gg    = (const int*)d_in[20];
    const int*   e_gp    = (const int*)d_in[21];
    const int*   e_pp    = (const int*)d_in[22];

    int Ng  = in_sizes[0] / F_IN;
    int Np  = in_sizes[1] / F_IN;
    int Egg = in_sizes[20] / 2;
    int Egp = in_sizes[21] / 2;
    int Epp = in_sizes[22] / 2;

    float *l_gene, *r_gene, *l_prot, *r_prot, *a_gene, *a_prot;
    float *agg_gg, *agg_gp, *agg_pp, *ubuf, *compW, *compb, *compq;
    int *cnt, *rowptr, *cursor, *sdst;
    cudaGetSymbolAddress((void**)&l_gene, g_l_gene);
    cudaGetSymbolAddress((void**)&r_gene, g_r_gene);
    cudaGetSymbolAddress((void**)&l_prot, g_l_prot);
    cudaGetSymbolAddress((void**)&r_prot, g_r_prot);
    cudaGetSymbolAddress((void**)&a_gene, g_a_gene);
    cudaGetSymbolAddress((void**)&a_prot, g_a_prot);
    cudaGetSymbolAddress((void**)&agg_gg, g_agg_gg);
    cudaGetSymbolAddress((void**)&agg_gp, g_agg_gp);
    cudaGetSymbolAddress((void**)&agg_pp, g_agg_pp);
    cudaGetSymbolAddress((void**)&ubuf, g_u);
    cudaGetSymbolAddress((void**)&compW, g_compW);
    cudaGetSymbolAddress((void**)&compb, g_compb);
    cudaGetSymbolAddress((void**)&compq, g_compq);
    cudaGetSymbolAddress((void**)&cnt, g_cnt);
    cudaGetSymbolAddress((void**)&rowptr, g_rowptr);
    cudaGetSymbolAddress((void**)&cursor, g_cursor);
    cudaGetSymbolAddress((void**)&sdst, g_sdst);

    float* compWg = compW;  float* compWp = compW + 128 * 256;
    float* compbg = compb;  float* compbp = compb + 128;
    float* compqg = compq;  float* compqp = compq + 128;

    float* u0 = ubuf;               // gene tails (mp0)
    float* u1 = ubuf + N_CAP;       // prot tails (mp1)
    float* u2 = ubuf + 2 * N_CAP;   // prot tails (mp2)

    cudaMemsetAsync(cnt, 0, (size_t)3 * N_CAP * sizeof(int), 0);
    cudaMemsetAsync(compW, 0, (size_t)2 * 128 * 256 * sizeof(float), 0);

    build_comp<<<192, 256>>>(alW, alb, arW, arb, qw,
                             Wl_gene, bl_gene, Wr_gene, br_gene,
                             Wl_prot, bl_prot, Wr_prot, br_prot,
                             compWg, compbg, compqg, compWp, compbp, compqp);

    int nbg = (Ng + BM - 1) / BM, nbp = (Np + BM - 1) / BM;
    proj_gemm<<<dim3(nbg, 2), 256>>>(x_gene, Ng, Wl_gene, bl_gene, l_gene,
                                     Wr_gene, br_gene, r_gene);
    proj_gemm<<<dim3(nbp, 2), 256>>>(x_prot, Np, Wl_prot, bl_prot, l_prot,
                                     Wr_prot, br_prot, r_prot);
    proj_gemm<<<dim3(nbg, 1), 256>>>(x_gene, Ng, compWg, compbg, a_gene,
                                     compWg, compbg, a_gene);
    proj_gemm<<<dim3(nbp, 1), 256>>>(x_prot, Np, compWp, compbp, a_prot,
                                     compWp, compbp, a_prot);

    u_extract<<<(Ng + 7) / 8, 256>>>(a_gene, Ng, compqg, sharp, 1, u0, u0, u0);
    u_extract<<<(Np + 7) / 8, 256>>>(a_prot, Np, compqp, sharp, 0, u1, u1, u2);

    // CSR build (segment = head node)
    edge_hist<<<(Egg + 255) / 256, 256>>>(e_gg, Egg, cnt + 0 * N_CAP);
    edge_hist<<<(Egp + 255) / 256, 256>>>(e_gp, Egp, cnt + 1 * N_CAP);
    edge_hist<<<(Epp + 255) / 256, 256>>>(e_pp, Epp, cnt + 2 * N_CAP);
    scan3<<<3, 1024>>>(cnt, rowptr, cursor, N_CAP);
    edge_scatter_idx<<<(Egg + 255) / 256, 256>>>(e_gg, Egg, cursor + 0 * N_CAP, sdst + 0 * E_CAP);
    edge_scatter_idx<<<(Egp + 255) / 256, 256>>>(e_gp, Egp, cursor + 1 * N_CAP, sdst + 1 * E_CAP);
    edge_scatter_idx<<<(Epp + 255) / 256, 256>>>(e_pp, Epp, cursor + 2 * N_CAP, sdst + 2 * E_CAP);

    // gather-aggregate, atomic-free, writes normalized agg
    agg_gather<<<(unsigned)(((size_t)Ng * 32 + 255) / 256), 256>>>(
        rowptr + 0 * N_CAP, cnt + 0 * N_CAP, sdst + 0 * E_CAP, u0, r_gene, agg_gg, Ng);
    agg_gather<<<(unsigned)(((size_t)Ng * 32 + 255) / 256), 256>>>(
        rowptr + 1 * N_CAP, cnt + 1 * N_CAP, sdst + 1 * E_CAP, u1, r_prot, agg_gp, Ng);
    agg_gather<<<(unsigned)(((size_t)Np * 32 + 255) / 256), 256>>>(
        rowptr + 2 * N_CAP, cnt + 2 * N_CAP, sdst + 2 * E_CAP, u2, r_prot, agg_pp, Np);

    float* out = (float*)d_out;
    combine_kernel<<<(unsigned)(((size_t)Ng * 32 + 255) / 256), 256>>>(agg_gg, agg_gp, l_gene, convgW, out, Ng, 1);
    combine_kernel<<<(unsigned)(((size_t)Np * 32 + 255) / 256), 256>>>(agg_pp, agg_pp, l_prot, convpW, out + (size_t)Ng * D, Np, 0);
}